// round 7
// baseline (speedup 1.0000x reference)
#include <cuda_runtime.h>
#include <cstdint>

// ---------------------------------------------------------------------------
// GRU layer, B=32, T=2048, D=256, H=256, fp32, masked update.
//   Kernel 1: gx = x @ W_ih + b_ih via warp mma.sync tf32 (3-term 2xTF32).
//   Kernel 2: persistent cluster recurrence with mbarrier handshake.
// R6 fix: mbarrier.arrive must be .release.cluster (default is release.CTA,
//         which does NOT order st.shared::cluster stores for remote readers
//         -> data race -> rel_err 2.3e-2 last round).
// ---------------------------------------------------------------------------

#define B_  32
#define T_  2048
#define D_  256
#define H_  256
#define G3_ 768

__device__ float g_gx[(size_t)B_ * T_ * G3_];

// ---------------- helpers ----------------
__device__ __forceinline__ unsigned long long pack2(float x, float y) {
    unsigned long long r;
    asm("mov.b64 %0, {%1, %2};" : "=l"(r) : "f"(x), "f"(y));
    return r;
}
__device__ __forceinline__ float2 unpack2(unsigned long long v) {
    float2 r;
    asm("mov.b64 {%0, %1}, %2;" : "=f"(r.x), "=f"(r.y) : "l"(v));
    return r;
}
__device__ __forceinline__ unsigned long long fma2(unsigned long long a,
                                                   unsigned long long b,
                                                   unsigned long long c) {
    unsigned long long d;
    asm("fma.rn.f32x2 %0, %1, %2, %3;" : "=l"(d) : "l"(a), "l"(b), "l"(c));
    return d;
}
__device__ __forceinline__ unsigned long long add2(unsigned long long a,
                                                   unsigned long long b) {
    unsigned long long d;
    asm("add.rn.f32x2 %0, %1, %2;" : "=l"(d) : "l"(a), "l"(b));
    return d;
}
__device__ __forceinline__ uint32_t smem_u32(const void* p) {
    uint32_t a;
    asm("{ .reg .u64 t; cvta.to.shared.u64 t, %1; cvt.u32.u64 %0, t; }"
        : "=r"(a) : "l"(p));
    return a;
}
__device__ __forceinline__ float sigmoid_fast(float x) {
    return __fdividef(1.0f, 1.0f + __expf(-x));
}
__device__ __forceinline__ float tanh_fast(float x) {
    float e = __expf(2.0f * x);
    return 1.0f - __fdividef(2.0f, e + 1.0f);
}
__device__ __forceinline__ uint32_t tf32_rna(float f) {
    uint32_t u;
    asm("cvt.rna.tf32.f32 %0, %1;" : "=r"(u) : "f"(f));
    return u;
}
__device__ __forceinline__ void mbar_wait(uint32_t addr, uint32_t parity) {
    uint32_t done;
    asm volatile(
        "{\n\t.reg .pred p;\n\t"
        "mbarrier.try_wait.parity.acquire.cluster.shared::cta.b64 p, [%1], %2;\n\t"
        "selp.b32 %0, 1, 0, p;\n\t}"
        : "=r"(done) : "r"(addr), "r"(parity) : "memory");
    if (!done) {
        asm volatile(
            "{\n\t.reg .pred P1;\n\t"
            "W0_%=:\n\t"
            "mbarrier.try_wait.parity.acquire.cluster.shared::cta.b64 P1, [%0], %1, 0x989680;\n\t"
            "@P1 bra.uni W1_%=;\n\t"
            "bra.uni W0_%=;\n\t"
            "W1_%=:\n\t}"
            :: "r"(addr), "r"(parity) : "memory");
    }
}

// ===========================================================================
// Kernel 1: gx = x @ W_ih + b_ih  (unchanged from passing R5)
// ===========================================================================
#define SM_AH 0
#define SM_AL 4224
#define SM_BH 8448
#define SM_BL 12672
#define SM_WORDS 16896   // 67584 bytes

__device__ __forceinline__ void mma_tf32(float c[4],
                                         uint32_t a0, uint32_t a1,
                                         uint32_t a2, uint32_t a3,
                                         uint32_t b0, uint32_t b1) {
    asm volatile(
        "mma.sync.aligned.m16n8k8.row.col.f32.tf32.tf32.f32 "
        "{%0,%1,%2,%3}, {%4,%5,%6,%7}, {%8,%9}, {%0,%1,%2,%3};"
        : "+f"(c[0]), "+f"(c[1]), "+f"(c[2]), "+f"(c[3])
        : "r"(a0), "r"(a1), "r"(a2), "r"(a3), "r"(b0), "r"(b1));
}

__global__ __launch_bounds__(256)
void gemm_gx_mma(const float* __restrict__ A,
                 const float* __restrict__ Bw,
                 const float* __restrict__ bias,
                 float* __restrict__ C)
{
    extern __shared__ uint32_t smu[];
    const int tid = threadIdx.x;
    const int wid = tid >> 5;
    const int lane = tid & 31;
    const int tg = lane >> 2;
    const int tk = lane & 3;

    const int warp_m = wid & 1;
    const int warp_n = wid >> 1;
    const int row0 = blockIdx.y * 128;
    const int col0 = blockIdx.x * 128;

    float acc[4][4][4];
#pragma unroll
    for (int i = 0; i < 4; i++)
#pragma unroll
        for (int j = 0; j < 4; j++)
#pragma unroll
            for (int q = 0; q < 4; q++) acc[i][j][q] = 0.0f;

    for (int c = 0; c < 8; c++) {
        const int k0 = c * 32;
        if (c) __syncthreads();

#pragma unroll
        for (int it = 0; it < 4; it++) {
            int idx = tid + it * 256;
            int r = idx >> 3;
            int q = (idx & 7) * 4;
            float4 v = *(const float4*)&A[(size_t)(row0 + r) * D_ + k0 + q];
            uint32_t base = r * 33 + q;
            uint32_t h;
            h = tf32_rna(v.x); smu[SM_AH + base + 0] = h;
            smu[SM_AL + base + 0] = tf32_rna(v.x - __uint_as_float(h));
            h = tf32_rna(v.y); smu[SM_AH + base + 1] = h;
            smu[SM_AL + base + 1] = tf32_rna(v.y - __uint_as_float(h));
            h = tf32_rna(v.z); smu[SM_AH + base + 2] = h;
            smu[SM_AL + base + 2] = tf32_rna(v.z - __uint_as_float(h));
            h = tf32_rna(v.w); smu[SM_AH + base + 3] = h;
            smu[SM_AL + base + 3] = tf32_rna(v.w - __uint_as_float(h));
        }

#pragma unroll
        for (int it = 0; it < 4; it++) {
            int idx = tid + it * 256;
            int kk = idx >> 5;
            int n4 = (idx & 31) * 4;
            float4 v = *(const float4*)&Bw[(size_t)(k0 + kk) * G3_ + col0 + n4];
            uint4 hi, lo;
            hi.x = tf32_rna(v.x); lo.x = tf32_rna(v.x - __uint_as_float(hi.x));
            hi.y = tf32_rna(v.y); lo.y = tf32_rna(v.y - __uint_as_float(hi.y));
            hi.z = tf32_rna(v.z); lo.z = tf32_rna(v.z - __uint_as_float(hi.z));
            hi.w = tf32_rna(v.w); lo.w = tf32_rna(v.w - __uint_as_float(hi.w));
            uint32_t base = kk * 132 + n4;
            *(uint4*)&smu[SM_BH + base] = hi;
            *(uint4*)&smu[SM_BL + base] = lo;
        }
        __syncthreads();

#pragma unroll
        for (int ks = 0; ks < 4; ks++) {
            const int kb = ks * 8;
            uint32_t bh[4][2], bl[4][2];
#pragma unroll
            for (int fn = 0; fn < 4; fn++) {
                int n = warp_n * 32 + fn * 8 + tg;
                bh[fn][0] = smu[SM_BH + (kb + tk) * 132 + n];
                bh[fn][1] = smu[SM_BH + (kb + tk + 4) * 132 + n];
                bl[fn][0] = smu[SM_BL + (kb + tk) * 132 + n];
                bl[fn][1] = smu[SM_BL + (kb + tk + 4) * 132 + n];
            }
#pragma unroll
            for (int fm = 0; fm < 4; fm++) {
                int r = warp_m * 64 + fm * 16 + tg;
                uint32_t ah0 = smu[SM_AH + r * 33 + kb + tk];
                uint32_t ah1 = smu[SM_AH + (r + 8) * 33 + kb + tk];
                uint32_t ah2 = smu[SM_AH + r * 33 + kb + tk + 4];
                uint32_t ah3 = smu[SM_AH + (r + 8) * 33 + kb + tk + 4];
                uint32_t al0 = smu[SM_AL + r * 33 + kb + tk];
                uint32_t al1 = smu[SM_AL + (r + 8) * 33 + kb + tk];
                uint32_t al2 = smu[SM_AL + r * 33 + kb + tk + 4];
                uint32_t al3 = smu[SM_AL + (r + 8) * 33 + kb + tk + 4];
#pragma unroll
                for (int fn = 0; fn < 4; fn++) {
                    mma_tf32(acc[fm][fn], ah0, ah1, ah2, ah3,
                             bh[fn][0], bh[fn][1]);
                    mma_tf32(acc[fm][fn], al0, al1, al2, al3,
                             bh[fn][0], bh[fn][1]);
                    mma_tf32(acc[fm][fn], ah0, ah1, ah2, ah3,
                             bl[fn][0], bl[fn][1]);
                }
            }
        }
    }

#pragma unroll
    for (int fm = 0; fm < 4; fm++) {
        int r1 = row0 + warp_m * 64 + fm * 16 + tg;
        int r2 = r1 + 8;
#pragma unroll
        for (int fn = 0; fn < 4; fn++) {
            int col = col0 + warp_n * 32 + fn * 8 + 2 * tk;
            float b0 = bias[col], b1 = bias[col + 1];
            float2 v0 = make_float2(acc[fm][fn][0] + b0, acc[fm][fn][1] + b1);
            float2 v1 = make_float2(acc[fm][fn][2] + b0, acc[fm][fn][3] + b1);
            *(float2*)&C[(size_t)r1 * G3_ + col] = v0;
            *(float2*)&C[(size_t)r2 * G3_ + col] = v1;
        }
    }
}

// ===========================================================================
// Kernel 2: recurrence, mbarrier-handshake (R6: release.cluster arrive).
// ===========================================================================
__global__ void __cluster_dims__(8, 1, 1) __launch_bounds__(384, 1)
gru_recur_kernel(const float* __restrict__ gx,
                 const int* __restrict__ mask,
                 const float* __restrict__ h0,
                 const float* __restrict__ W_hh,
                 const float* __restrict__ b_hh,
                 float* __restrict__ out)
{
    __shared__ __align__(16) float2 sh_h[2][H_];
    __shared__ __align__(16) unsigned long long red[4][96];
    __shared__ __align__(8)  unsigned long long mbar[2];
    __shared__ uint32_t mbits[2][64];

    const int tid = threadIdx.x;
    const int j = tid % 96;
    const int s = tid / 96;
    uint32_t rank;
    asm("mov.u32 %0, %%cluster_ctarank;" : "=r"(rank));
    const int cid = blockIdx.x >> 3;
    const int b0  = cid * 2;

    const int piece = j >> 5;
    const int cIn   = j & 31;
    const int gcol  = piece * 256 + (int)rank * 32 + cIn;
    const int k0    = s * 64;

    unsigned long long wp[64];
#pragma unroll
    for (int kk = 0; kk < 64; kk++) {
        float w = W_hh[(size_t)(k0 + kk) * G3_ + gcol];
        wp[kk] = pack2(w, w);
    }

    for (int k = tid; k < H_; k += 384)
        sh_h[0][k] = make_float2(h0[(size_t)b0 * H_ + k],
                                 h0[(size_t)(b0 + 1) * H_ + k]);
    for (int w = tid; w < 128; w += 384) {
        int bbw = w >> 6, word = w & 63;
        const int* mp = mask + (size_t)(b0 + bbw) * T_ + word * 32;
        uint32_t bits = 0;
#pragma unroll
        for (int i = 0; i < 32; i++) bits |= (mp[i] != 0 ? 1u : 0u) << i;
        mbits[bbw][word] = bits;
    }
    const uint32_t sh_base  = smem_u32(&sh_h[0][0]);
    const uint32_t mbar_la  = smem_u32(&mbar[0]);
    if (tid == 0) {
        asm volatile("mbarrier.init.shared.b64 [%0], %1;"
                     :: "r"(mbar_la), "r"(64u) : "memory");
        asm volatile("mbarrier.init.shared.b64 [%0], %1;"
                     :: "r"(mbar_la + 8), "r"(64u) : "memory");
    }
    __syncthreads();
    asm volatile("barrier.cluster.arrive.aligned;" ::: "memory");
    asm volatile("barrier.cluster.wait.aligned;" ::: "memory");

    float bh_r = 0.f, bh_z = 0.f, bh_n = 0.f;
    int cc = 0, bb = 0, hcol = 0;
    const float* gx_b = nullptr;
    float* out_b = nullptr;
    float gr0 = 0.f, gz0 = 0.f, gn0 = 0.f;
    float gr1 = 0.f, gz1 = 0.f, gn1 = 0.f;
    if (tid < 64) {
        cc = tid & 31;
        bb = tid >> 5;
        hcol = (int)rank * 32 + cc;
        bh_r = b_hh[hcol];
        bh_z = b_hh[256 + hcol];
        bh_n = b_hh[512 + hcol];
        gx_b  = gx  + (size_t)(b0 + bb) * T_ * G3_;
        out_b = out + (size_t)(b0 + bb) * T_ * H_;
        const float* g0 = gx_b + hcol;
        gr0 = g0[0];   gz0 = g0[256];       gn0 = g0[512];
        gr1 = g0[G3_]; gz1 = g0[G3_ + 256]; gn1 = g0[G3_ + 512];
    }

    uint32_t rd_src0 = 0, rd_dst0 = 0, rd_bar = 0;
    if (tid >= 64 && tid < 128) {
        int e  = tid - 64;
        int rr = e >> 3;
        int q4 = (e & 7) * 4;
        uint32_t la = sh_base + (uint32_t)(((int)rank * 32 + q4) * 8);
        asm("mapa.shared::cluster.u32 %0, %1, %2;"
            : "=r"(rd_dst0) : "r"(la), "r"((uint32_t)rr));
        rd_src0 = la;
        asm("mapa.shared::cluster.u32 %0, %1, %2;"
            : "=r"(rd_bar) : "r"(mbar_la), "r"((uint32_t)rr));
    }

    uint32_t ph0 = 0, ph1 = 0;

    for (int t = 0; t < T_; t++) {
        const int p = t & 1;

        if (t) {
            if (p == 0) { mbar_wait(mbar_la, ph0);     ph0 ^= 1; }
            else        { mbar_wait(mbar_la + 8, ph1); ph1 ^= 1; }
        }

        float gxr = 0.f, gxz = 0.f, gxn = 0.f;
        int m = 1;
        if (tid < 64) {
            gxr = gr0; gxz = gz0; gxn = gn0;
            gr0 = gr1; gz0 = gz1; gn0 = gn1;
            m = (int)((mbits[bb][t >> 5] >> (t & 31)) & 1u);
            if (t + 2 < T_) {
                const float* g2 = gx_b + (size_t)(t + 2) * G3_ + hcol;
                gr1 = g2[0]; gz1 = g2[256]; gn1 = g2[512];
            }
        }

        unsigned long long a0 = 0ull, a1 = 0ull;
        const ulonglong2* hp = (const ulonglong2*)&sh_h[p][k0];
#pragma unroll
        for (int kk = 0; kk < 32; kk++) {
            ulonglong2 hv = hp[kk];
            a0 = fma2(wp[2 * kk],     hv.x, a0);
            a1 = fma2(wp[2 * kk + 1], hv.y, a1);
        }
        red[s][j] = add2(a0, a1);
        __syncthreads();

        if (tid < 64) {
            unsigned long long rr_ = add2(add2(red[0][cc], red[1][cc]),
                                          add2(red[2][cc], red[3][cc]));
            unsigned long long zz_ = add2(add2(red[0][32 + cc], red[1][32 + cc]),
                                          add2(red[2][32 + cc], red[3][32 + cc]));
            unsigned long long nn_ = add2(add2(red[0][64 + cc], red[1][64 + cc]),
                                          add2(red[2][64 + cc], red[3][64 + cc]));
            float2 vr = unpack2(rr_), vz = unpack2(zz_), vn = unpack2(nn_);
            float ghr = bb ? vr.y : vr.x;
            float ghz = bb ? vz.y : vz.x;
            float ghn = bb ? vn.y : vn.x;
            float2 ho = sh_h[p][hcol];
            float hold = bb ? ho.y : ho.x;

            float r  = sigmoid_fast(gxr + ghr + bh_r);
            float z  = sigmoid_fast(gxz + ghz + bh_z);
            float n  = tanh_fast(gxn + r * (ghn + bh_n));
            float hnew = (1.0f - z) * n + z * hold;
            if (!m) hnew = hold;

            out_b[(size_t)t * H_ + hcol] = hnew;
            *((float*)&sh_h[1 - p][0] + hcol * 2 + bb) = hnew;
        }

        if (tid < 128) {
            asm volatile("bar.sync 1, 128;" ::: "memory");
            if (tid >= 64) {
                uint32_t boff = (uint32_t)((1 - p) * (H_ * 8));
                uint32_t srcb = rd_src0 + boff;
                uint32_t dstb = rd_dst0 + boff;
#pragma unroll
                for (int i = 0; i < 4; i++) {
                    unsigned long long v;
                    asm volatile("ld.shared.b64 %0, [%1];"
                                 : "=l"(v) : "r"(srcb + i * 8));
                    asm volatile("st.shared::cluster.b64 [%0], %1;"
                                 :: "r"(dstb + i * 8), "l"(v) : "memory");
                }
                // R6 FIX: release at CLUSTER scope so remote acquire-waiters
                // observe the st.shared::cluster stores above.
                uint32_t rb = rd_bar + (uint32_t)((1 - p) * 8);
                asm volatile(
                    "mbarrier.arrive.release.cluster.shared::cluster.b64 _, [%0];"
                    :: "r"(rb) : "memory");
            }
        }
    }

    asm volatile("barrier.cluster.arrive.aligned;" ::: "memory");
    asm volatile("barrier.cluster.wait.aligned;" ::: "memory");
}

// ===========================================================================
// Launch
// ===========================================================================
extern "C" void kernel_launch(void* const* d_in, const int* in_sizes, int n_in,
                              void* d_out, int out_size)
{
    const float* x    = (const float*)d_in[0];
    const int*   mask = (const int*)d_in[1];
    const float* h0   = (const float*)d_in[2];
    const float* W_ih = (const float*)d_in[3];
    const float* W_hh = (const float*)d_in[4];
    const float* b_ih = (const float*)d_in[5];
    const float* b_hh = (const float*)d_in[6];
    float* out = (float*)d_out;

    float* gx;
    cudaGetSymbolAddress((void**)&gx, g_gx);

    cudaFuncSetAttribute(gemm_gx_mma,
                         cudaFuncAttributeMaxDynamicSharedMemorySize,
                         SM_WORDS * 4);

    dim3 g1(G3_ / 128, (B_ * T_) / 128);   // (6, 512)
    gemm_gx_mma<<<g1, 256, SM_WORDS * 4>>>(x, W_ih, b_ih, gx);

    gru_recur_kernel<<<128, 384>>>(gx, mask, h0, W_hh, b_hh, out);
}

// round 8
// speedup vs baseline: 1.0052x; 1.0052x over previous
#include <cuda_runtime.h>
#include <cstdint>

// ---------------------------------------------------------------------------
// GRU layer, B=32, T=2048, D=256, H=256, fp32, masked update.
//   Kernel 1: gx = x @ W_ih + b_ih via warp mma.sync tf32 (3-term 2xTF32).
//   Kernel 2: persistent cluster recurrence with mbarrier handshake.
// R7 fix: W_hh register packing along k (wq[32] b64 = 64 regs) instead of
//         dup-packed batch pairs (128 regs) -> eliminates local-memory
//         spills that dominated all prior recurrence versions (~146 regs
//         vs 170 cap with ~180 demand).
// ---------------------------------------------------------------------------

#define B_  32
#define T_  2048
#define D_  256
#define H_  256
#define G3_ 768

__device__ float g_gx[(size_t)B_ * T_ * G3_];

// ---------------- helpers ----------------
__device__ __forceinline__ unsigned long long pack2(float x, float y) {
    unsigned long long r;
    asm("mov.b64 %0, {%1, %2};" : "=l"(r) : "f"(x), "f"(y));
    return r;
}
__device__ __forceinline__ float2 unpack2(unsigned long long v) {
    float2 r;
    asm("mov.b64 {%0, %1}, %2;" : "=f"(r.x), "=f"(r.y) : "l"(v));
    return r;
}
__device__ __forceinline__ unsigned long long fma2(unsigned long long a,
                                                   unsigned long long b,
                                                   unsigned long long c) {
    unsigned long long d;
    asm("fma.rn.f32x2 %0, %1, %2, %3;" : "=l"(d) : "l"(a), "l"(b), "l"(c));
    return d;
}
__device__ __forceinline__ unsigned long long add2(unsigned long long a,
                                                   unsigned long long b) {
    unsigned long long d;
    asm("add.rn.f32x2 %0, %1, %2;" : "=l"(d) : "l"(a), "l"(b));
    return d;
}
__device__ __forceinline__ uint32_t smem_u32(const void* p) {
    uint32_t a;
    asm("{ .reg .u64 t; cvta.to.shared.u64 t, %1; cvt.u32.u64 %0, t; }"
        : "=r"(a) : "l"(p));
    return a;
}
__device__ __forceinline__ float sigmoid_fast(float x) {
    return __fdividef(1.0f, 1.0f + __expf(-x));
}
__device__ __forceinline__ float tanh_fast(float x) {
    float e = __expf(2.0f * x);
    return 1.0f - __fdividef(2.0f, e + 1.0f);
}
__device__ __forceinline__ uint32_t tf32_rna(float f) {
    uint32_t u;
    asm("cvt.rna.tf32.f32 %0, %1;" : "=r"(u) : "f"(f));
    return u;
}
__device__ __forceinline__ void mbar_wait(uint32_t addr, uint32_t parity) {
    uint32_t done;
    asm volatile(
        "{\n\t.reg .pred p;\n\t"
        "mbarrier.try_wait.parity.acquire.cluster.shared::cta.b64 p, [%1], %2;\n\t"
        "selp.b32 %0, 1, 0, p;\n\t}"
        : "=r"(done) : "r"(addr), "r"(parity) : "memory");
    if (!done) {
        asm volatile(
            "{\n\t.reg .pred P1;\n\t"
            "W0_%=:\n\t"
            "mbarrier.try_wait.parity.acquire.cluster.shared::cta.b64 P1, [%0], %1, 0x989680;\n\t"
            "@P1 bra.uni W1_%=;\n\t"
            "bra.uni W0_%=;\n\t"
            "W1_%=:\n\t}"
            :: "r"(addr), "r"(parity) : "memory");
    }
}

// ===========================================================================
// Kernel 1: gx = x @ W_ih + b_ih  (unchanged from passing R5)
// ===========================================================================
#define SM_AH 0
#define SM_AL 4224
#define SM_BH 8448
#define SM_BL 12672
#define SM_WORDS 16896   // 67584 bytes

__device__ __forceinline__ void mma_tf32(float c[4],
                                         uint32_t a0, uint32_t a1,
                                         uint32_t a2, uint32_t a3,
                                         uint32_t b0, uint32_t b1) {
    asm volatile(
        "mma.sync.aligned.m16n8k8.row.col.f32.tf32.tf32.f32 "
        "{%0,%1,%2,%3}, {%4,%5,%6,%7}, {%8,%9}, {%0,%1,%2,%3};"
        : "+f"(c[0]), "+f"(c[1]), "+f"(c[2]), "+f"(c[3])
        : "r"(a0), "r"(a1), "r"(a2), "r"(a3), "r"(b0), "r"(b1));
}

__global__ __launch_bounds__(256)
void gemm_gx_mma(const float* __restrict__ A,
                 const float* __restrict__ Bw,
                 const float* __restrict__ bias,
                 float* __restrict__ C)
{
    extern __shared__ uint32_t smu[];
    const int tid = threadIdx.x;
    const int wid = tid >> 5;
    const int lane = tid & 31;
    const int tg = lane >> 2;
    const int tk = lane & 3;

    const int warp_m = wid & 1;
    const int warp_n = wid >> 1;
    const int row0 = blockIdx.y * 128;
    const int col0 = blockIdx.x * 128;

    float acc[4][4][4];
#pragma unroll
    for (int i = 0; i < 4; i++)
#pragma unroll
        for (int j = 0; j < 4; j++)
#pragma unroll
            for (int q = 0; q < 4; q++) acc[i][j][q] = 0.0f;

    for (int c = 0; c < 8; c++) {
        const int k0 = c * 32;
        if (c) __syncthreads();

#pragma unroll
        for (int it = 0; it < 4; it++) {
            int idx = tid + it * 256;
            int r = idx >> 3;
            int q = (idx & 7) * 4;
            float4 v = *(const float4*)&A[(size_t)(row0 + r) * D_ + k0 + q];
            uint32_t base = r * 33 + q;
            uint32_t h;
            h = tf32_rna(v.x); smu[SM_AH + base + 0] = h;
            smu[SM_AL + base + 0] = tf32_rna(v.x - __uint_as_float(h));
            h = tf32_rna(v.y); smu[SM_AH + base + 1] = h;
            smu[SM_AL + base + 1] = tf32_rna(v.y - __uint_as_float(h));
            h = tf32_rna(v.z); smu[SM_AH + base + 2] = h;
            smu[SM_AL + base + 2] = tf32_rna(v.z - __uint_as_float(h));
            h = tf32_rna(v.w); smu[SM_AH + base + 3] = h;
            smu[SM_AL + base + 3] = tf32_rna(v.w - __uint_as_float(h));
        }

#pragma unroll
        for (int it = 0; it < 4; it++) {
            int idx = tid + it * 256;
            int kk = idx >> 5;
            int n4 = (idx & 31) * 4;
            float4 v = *(const float4*)&Bw[(size_t)(k0 + kk) * G3_ + col0 + n4];
            uint4 hi, lo;
            hi.x = tf32_rna(v.x); lo.x = tf32_rna(v.x - __uint_as_float(hi.x));
            hi.y = tf32_rna(v.y); lo.y = tf32_rna(v.y - __uint_as_float(hi.y));
            hi.z = tf32_rna(v.z); lo.z = tf32_rna(v.z - __uint_as_float(hi.z));
            hi.w = tf32_rna(v.w); lo.w = tf32_rna(v.w - __uint_as_float(hi.w));
            uint32_t base = kk * 132 + n4;
            *(uint4*)&smu[SM_BH + base] = hi;
            *(uint4*)&smu[SM_BL + base] = lo;
        }
        __syncthreads();

#pragma unroll
        for (int ks = 0; ks < 4; ks++) {
            const int kb = ks * 8;
            uint32_t bh[4][2], bl[4][2];
#pragma unroll
            for (int fn = 0; fn < 4; fn++) {
                int n = warp_n * 32 + fn * 8 + tg;
                bh[fn][0] = smu[SM_BH + (kb + tk) * 132 + n];
                bh[fn][1] = smu[SM_BH + (kb + tk + 4) * 132 + n];
                bl[fn][0] = smu[SM_BL + (kb + tk) * 132 + n];
                bl[fn][1] = smu[SM_BL + (kb + tk + 4) * 132 + n];
            }
#pragma unroll
            for (int fm = 0; fm < 4; fm++) {
                int r = warp_m * 64 + fm * 16 + tg;
                uint32_t ah0 = smu[SM_AH + r * 33 + kb + tk];
                uint32_t ah1 = smu[SM_AH + (r + 8) * 33 + kb + tk];
                uint32_t ah2 = smu[SM_AH + r * 33 + kb + tk + 4];
                uint32_t ah3 = smu[SM_AH + (r + 8) * 33 + kb + tk + 4];
                uint32_t al0 = smu[SM_AL + r * 33 + kb + tk];
                uint32_t al1 = smu[SM_AL + (r + 8) * 33 + kb + tk];
                uint32_t al2 = smu[SM_AL + r * 33 + kb + tk + 4];
                uint32_t al3 = smu[SM_AL + (r + 8) * 33 + kb + tk + 4];
#pragma unroll
                for (int fn = 0; fn < 4; fn++) {
                    mma_tf32(acc[fm][fn], ah0, ah1, ah2, ah3,
                             bh[fn][0], bh[fn][1]);
                    mma_tf32(acc[fm][fn], al0, al1, al2, al3,
                             bh[fn][0], bh[fn][1]);
                    mma_tf32(acc[fm][fn], ah0, ah1, ah2, ah3,
                             bl[fn][0], bl[fn][1]);
                }
            }
        }
    }

#pragma unroll
    for (int fm = 0; fm < 4; fm++) {
        int r1 = row0 + warp_m * 64 + fm * 16 + tg;
        int r2 = r1 + 8;
#pragma unroll
        for (int fn = 0; fn < 4; fn++) {
            int col = col0 + warp_n * 32 + fn * 8 + 2 * tk;
            float b0 = bias[col], b1 = bias[col + 1];
            float2 v0 = make_float2(acc[fm][fn][0] + b0, acc[fm][fn][1] + b1);
            float2 v1 = make_float2(acc[fm][fn][2] + b0, acc[fm][fn][3] + b1);
            *(float2*)&C[(size_t)r1 * G3_ + col] = v0;
            *(float2*)&C[(size_t)r2 * G3_ + col] = v1;
        }
    }
}

// ===========================================================================
// Kernel 2: recurrence. h layout [batch][k]; W packed along k (wq[32] b64).
// Per thread (j = gate col, s = k-quarter): a0/a1 = (even-k, odd-k) partial
// sums for batch0/batch1. Epilogue sums quarters + horizontal add.
// ===========================================================================
__global__ void __cluster_dims__(8, 1, 1) __launch_bounds__(384, 1)
gru_recur_kernel(const float* __restrict__ gx,
                 const int* __restrict__ mask,
                 const float* __restrict__ h0,
                 const float* __restrict__ W_hh,
                 const float* __restrict__ b_hh,
                 float* __restrict__ out)
{
    __shared__ __align__(16) float sh_h[2][2][H_];         // [buf][batch][k]
    __shared__ __align__(16) unsigned long long red[2][4][96]; // [batch][s][j]
    __shared__ __align__(8)  unsigned long long mbar[2];
    __shared__ uint32_t mbits[2][64];

    const int tid = threadIdx.x;
    const int j = tid % 96;
    const int s = tid / 96;
    uint32_t rank;
    asm("mov.u32 %0, %%cluster_ctarank;" : "=r"(rank));
    const int cid = blockIdx.x >> 3;
    const int b0  = cid * 2;

    const int piece = j >> 5;
    const int cIn   = j & 31;
    const int gcol  = piece * 256 + (int)rank * 32 + cIn;
    const int k0    = s * 64;

    // ---- W_hh slice: 64 k-values packed as 32 b64 (k, k+1) -> 64 regs ----
    unsigned long long wq[32];
#pragma unroll
    for (int i = 0; i < 32; i++) {
        wq[i] = pack2(W_hh[(size_t)(k0 + 2 * i) * G3_ + gcol],
                      W_hh[(size_t)(k0 + 2 * i + 1) * G3_ + gcol]);
    }

    // ---- init h buffer 0 ([batch][k]), mask bitmasks, mbarriers ----
    for (int i = tid; i < 2 * H_; i += 384) {
        int bbw = i >> 8, k = i & 255;
        sh_h[0][bbw][k] = h0[(size_t)(b0 + bbw) * H_ + k];
    }
    for (int w = tid; w < 128; w += 384) {
        int bbw = w >> 6, word = w & 63;
        const int* mp = mask + (size_t)(b0 + bbw) * T_ + word * 32;
        uint32_t bits = 0;
#pragma unroll
        for (int i = 0; i < 32; i++) bits |= (mp[i] != 0 ? 1u : 0u) << i;
        mbits[bbw][word] = bits;
    }
    const uint32_t sh_base  = smem_u32(&sh_h[0][0][0]);
    const uint32_t mbar_la  = smem_u32(&mbar[0]);
    if (tid == 0) {
        asm volatile("mbarrier.init.shared.b64 [%0], %1;"
                     :: "r"(mbar_la), "r"(64u) : "memory");
        asm volatile("mbarrier.init.shared.b64 [%0], %1;"
                     :: "r"(mbar_la + 8), "r"(64u) : "memory");
    }
    __syncthreads();
    asm volatile("barrier.cluster.arrive.aligned;" ::: "memory");
    asm volatile("barrier.cluster.wait.aligned;" ::: "memory");

    // ---- epilogue-thread constants (threads 0..63) ----
    float bh_r = 0.f, bh_z = 0.f, bh_n = 0.f;
    int cc = 0, bb = 0, hcol = 0;
    const float* gx_b = nullptr;
    float* out_b = nullptr;
    float gr0 = 0.f, gz0 = 0.f, gn0 = 0.f;
    float gr1 = 0.f, gz1 = 0.f, gn1 = 0.f;
    if (tid < 64) {
        cc = tid & 31;
        bb = tid >> 5;
        hcol = (int)rank * 32 + cc;
        bh_r = b_hh[hcol];
        bh_z = b_hh[256 + hcol];
        bh_n = b_hh[512 + hcol];
        gx_b  = gx  + (size_t)(b0 + bb) * T_ * G3_;
        out_b = out + (size_t)(b0 + bb) * T_ * H_;
        const float* g0 = gx_b + hcol;
        gr0 = g0[0];   gz0 = g0[256];       gn0 = g0[512];
        gr1 = g0[G3_]; gz1 = g0[G3_ + 256]; gn1 = g0[G3_ + 512];
    }

    // ---- redistribution-thread constants (threads 64..127) ----
    // e = tid-64; peer rr = e>>3; q = e&7 covers 8 floats of our 64-float
    // block {b0 cols, b1 cols}: batch = q>>2, col8 = (q&3)*8.
    uint32_t rd_src0 = 0, rd_dst0 = 0, rd_bar = 0;
    if (tid >= 64 && tid < 128) {
        int e  = tid - 64;
        int rr = e >> 3;
        int q  = e & 7;
        int fo = (q >> 2) * H_ + (int)rank * 32 + (q & 3) * 8;  // float offset
        uint32_t la = sh_base + (uint32_t)(fo * 4);
        asm("mapa.shared::cluster.u32 %0, %1, %2;"
            : "=r"(rd_dst0) : "r"(la), "r"((uint32_t)rr));
        rd_src0 = la;
        asm("mapa.shared::cluster.u32 %0, %1, %2;"
            : "=r"(rd_bar) : "r"(mbar_la), "r"((uint32_t)rr));
    }

    uint32_t ph0 = 0, ph1 = 0;

    for (int t = 0; t < T_; t++) {
        const int p = t & 1;

        if (t) {
            if (p == 0) { mbar_wait(mbar_la, ph0);     ph0 ^= 1; }
            else        { mbar_wait(mbar_la + 8, ph1); ph1 ^= 1; }
        }

        float gxr = 0.f, gxz = 0.f, gxn = 0.f;
        int m = 1;
        if (tid < 64) {
            gxr = gr0; gxz = gz0; gxn = gn0;
            gr0 = gr1; gz0 = gz1; gn0 = gn1;
            m = (int)((mbits[bb][t >> 5] >> (t & 31)) & 1u);
            if (t + 2 < T_) {
                const float* g2 = gx_b + (size_t)(t + 2) * G3_ + hcol;
                gr1 = g2[0]; gz1 = g2[256]; gn1 = g2[512];
            }
        }

        // ---- FMA: 2 batches x 32 fma2, W regs shared across batches ----
        unsigned long long a0 = 0ull, a1 = 0ull;
        const ulonglong2* hp0 = (const ulonglong2*)&sh_h[p][0][k0];
        const ulonglong2* hp1 = (const ulonglong2*)&sh_h[p][1][k0];
#pragma unroll
        for (int kk = 0; kk < 16; kk++) {
            ulonglong2 hv = hp0[kk];                 // 4 h of batch0
            a0 = fma2(wq[2 * kk],     hv.x, a0);
            a0 = fma2(wq[2 * kk + 1], hv.y, a0);
        }
#pragma unroll
        for (int kk = 0; kk < 16; kk++) {
            ulonglong2 hv = hp1[kk];                 // 4 h of batch1
            a1 = fma2(wq[2 * kk],     hv.x, a1);
            a1 = fma2(wq[2 * kk + 1], hv.y, a1);
        }
        red[0][s][j] = a0;
        red[1][s][j] = a1;
        __syncthreads();

        // ---- epilogue ----
        if (tid < 64) {
            unsigned long long rr_ = add2(add2(red[bb][0][cc], red[bb][1][cc]),
                                          add2(red[bb][2][cc], red[bb][3][cc]));
            unsigned long long zz_ = add2(add2(red[bb][0][32 + cc], red[bb][1][32 + cc]),
                                          add2(red[bb][2][32 + cc], red[bb][3][32 + cc]));
            unsigned long long nn_ = add2(add2(red[bb][0][64 + cc], red[bb][1][64 + cc]),
                                          add2(red[bb][2][64 + cc], red[bb][3][64 + cc]));
            float2 vr = unpack2(rr_), vz = unpack2(zz_), vn = unpack2(nn_);
            float ghr = vr.x + vr.y;
            float ghz = vz.x + vz.y;
            float ghn = vn.x + vn.y;
            float hold = sh_h[p][bb][hcol];

            float r  = sigmoid_fast(gxr + ghr + bh_r);
            float z  = sigmoid_fast(gxz + ghz + bh_z);
            float n  = tanh_fast(gxn + r * (ghn + bh_n));
            float hnew = (1.0f - z) * n + z * hold;
            if (!m) hnew = hold;

            out_b[(size_t)t * H_ + hcol] = hnew;
            sh_h[1 - p][bb][hcol] = hnew;            // local staging
        }

        if (tid < 128) {
            asm volatile("bar.sync 1, 128;" ::: "memory");
            if (tid >= 64) {
                uint32_t boff = (uint32_t)((1 - p) * (2 * H_ * 4));
                uint32_t srcb = rd_src0 + boff;
                uint32_t dstb = rd_dst0 + boff;
#pragma unroll
                for (int i = 0; i < 4; i++) {
                    unsigned long long v;
                    asm volatile("ld.shared.b64 %0, [%1];"
                                 : "=l"(v) : "r"(srcb + i * 8));
                    asm volatile("st.shared::cluster.b64 [%0], %1;"
                                 :: "r"(dstb + i * 8), "l"(v) : "memory");
                }
                uint32_t rb = rd_bar + (uint32_t)((1 - p) * 8);
                asm volatile(
                    "mbarrier.arrive.release.cluster.shared::cluster.b64 _, [%0];"
                    :: "r"(rb) : "memory");
            }
        }
    }

    asm volatile("barrier.cluster.arrive.aligned;" ::: "memory");
    asm volatile("barrier.cluster.wait.aligned;" ::: "memory");
}

// ===========================================================================
// Launch
// ===========================================================================
extern "C" void kernel_launch(void* const* d_in, const int* in_sizes, int n_in,
                              void* d_out, int out_size)
{
    const float* x    = (const float*)d_in[0];
    const int*   mask = (const int*)d_in[1];
    const float* h0   = (const float*)d_in[2];
    const float* W_ih = (const float*)d_in[3];
    const float* W_hh = (const float*)d_in[4];
    const float* b_ih = (const float*)d_in[5];
    const float* b_hh = (const float*)d_in[6];
    float* out = (float*)d_out;

    float* gx;
    cudaGetSymbolAddress((void**)&gx, g_gx);

    cudaFuncSetAttribute(gemm_gx_mma,
                         cudaFuncAttributeMaxDynamicSharedMemorySize,
                         SM_WORDS * 4);

    dim3 g1(G3_ / 128, (B_ * T_) / 128);   // (6, 512)
    gemm_gx_mma<<<g1, 256, SM_WORDS * 4>>>(x, W_ih, b_ih, gx);

    gru_recur_kernel<<<128, 384>>>(gx, mask, h0, W_hh, b_hh, out);
}

// round 9
// speedup vs baseline: 1.7040x; 1.6952x over previous
#include <cuda_runtime.h>
#include <cstdint>

// ---------------------------------------------------------------------------
// GRU layer, B=32, T=2048, D=256, H=256, fp32, masked update.
//   Kernel 1: gx = x @ W_ih + b_ih via warp mma.sync tf32 (3-term 2xTF32).
//   Kernel 2: persistent cluster recurrence.
// R8 redesign of the h-exchange: st.async (tx-counted remote stores) replaces
// st.shared::cluster + 64x arrive.release.cluster + bar.sync + pusher warps.
// Epilogue pushes directly; mbarrier re-armed via arrive.expect_tx(2048B).
// ---------------------------------------------------------------------------

#define B_  32
#define T_  2048
#define D_  256
#define H_  256
#define G3_ 768

__device__ float g_gx[(size_t)B_ * T_ * G3_];

// ---------------- helpers ----------------
__device__ __forceinline__ unsigned long long pack2(float x, float y) {
    unsigned long long r;
    asm("mov.b64 %0, {%1, %2};" : "=l"(r) : "f"(x), "f"(y));
    return r;
}
__device__ __forceinline__ float2 unpack2(unsigned long long v) {
    float2 r;
    asm("mov.b64 {%0, %1}, %2;" : "=f"(r.x), "=f"(r.y) : "l"(v));
    return r;
}
__device__ __forceinline__ unsigned long long fma2(unsigned long long a,
                                                   unsigned long long b,
                                                   unsigned long long c) {
    unsigned long long d;
    asm("fma.rn.f32x2 %0, %1, %2, %3;" : "=l"(d) : "l"(a), "l"(b), "l"(c));
    return d;
}
__device__ __forceinline__ unsigned long long add2(unsigned long long a,
                                                   unsigned long long b) {
    unsigned long long d;
    asm("add.rn.f32x2 %0, %1, %2;" : "=l"(d) : "l"(a), "l"(b));
    return d;
}
__device__ __forceinline__ uint32_t smem_u32(const void* p) {
    uint32_t a;
    asm("{ .reg .u64 t; cvta.to.shared.u64 t, %1; cvt.u32.u64 %0, t; }"
        : "=r"(a) : "l"(p));
    return a;
}
__device__ __forceinline__ float sigmoid_fast(float x) {
    return __fdividef(1.0f, 1.0f + __expf(-x));
}
__device__ __forceinline__ float tanh_fast(float x) {
    float e = __expf(2.0f * x);
    return 1.0f - __fdividef(2.0f, e + 1.0f);
}
__device__ __forceinline__ uint32_t tf32_rna(float f) {
    uint32_t u;
    asm("cvt.rna.tf32.f32 %0, %1;" : "=r"(u) : "f"(f));
    return u;
}
__device__ __forceinline__ void mbar_wait(uint32_t addr, uint32_t parity) {
    uint32_t done;
    asm volatile(
        "{\n\t.reg .pred p;\n\t"
        "mbarrier.try_wait.parity.acquire.cta.shared::cta.b64 p, [%1], %2;\n\t"
        "selp.b32 %0, 1, 0, p;\n\t}"
        : "=r"(done) : "r"(addr), "r"(parity) : "memory");
    if (!done) {
        asm volatile(
            "{\n\t.reg .pred P1;\n\t"
            "W0_%=:\n\t"
            "mbarrier.try_wait.parity.acquire.cta.shared::cta.b64 P1, [%0], %1, 0x989680;\n\t"
            "@P1 bra.uni W1_%=;\n\t"
            "bra.uni W0_%=;\n\t"
            "W1_%=:\n\t}"
            :: "r"(addr), "r"(parity) : "memory");
    }
}

// ===========================================================================
// Kernel 1: gx = x @ W_ih + b_ih  (unchanged from passing R5)
// ===========================================================================
#define SM_AH 0
#define SM_AL 4224
#define SM_BH 8448
#define SM_BL 12672
#define SM_WORDS 16896   // 67584 bytes

__device__ __forceinline__ void mma_tf32(float c[4],
                                         uint32_t a0, uint32_t a1,
                                         uint32_t a2, uint32_t a3,
                                         uint32_t b0, uint32_t b1) {
    asm volatile(
        "mma.sync.aligned.m16n8k8.row.col.f32.tf32.tf32.f32 "
        "{%0,%1,%2,%3}, {%4,%5,%6,%7}, {%8,%9}, {%0,%1,%2,%3};"
        : "+f"(c[0]), "+f"(c[1]), "+f"(c[2]), "+f"(c[3])
        : "r"(a0), "r"(a1), "r"(a2), "r"(a3), "r"(b0), "r"(b1));
}

__global__ __launch_bounds__(256)
void gemm_gx_mma(const float* __restrict__ A,
                 const float* __restrict__ Bw,
                 const float* __restrict__ bias,
                 float* __restrict__ C)
{
    extern __shared__ uint32_t smu[];
    const int tid = threadIdx.x;
    const int wid = tid >> 5;
    const int lane = tid & 31;
    const int tg = lane >> 2;
    const int tk = lane & 3;

    const int warp_m = wid & 1;
    const int warp_n = wid >> 1;
    const int row0 = blockIdx.y * 128;
    const int col0 = blockIdx.x * 128;

    float acc[4][4][4];
#pragma unroll
    for (int i = 0; i < 4; i++)
#pragma unroll
        for (int j = 0; j < 4; j++)
#pragma unroll
            for (int q = 0; q < 4; q++) acc[i][j][q] = 0.0f;

    for (int c = 0; c < 8; c++) {
        const int k0 = c * 32;
        if (c) __syncthreads();

#pragma unroll
        for (int it = 0; it < 4; it++) {
            int idx = tid + it * 256;
            int r = idx >> 3;
            int q = (idx & 7) * 4;
            float4 v = *(const float4*)&A[(size_t)(row0 + r) * D_ + k0 + q];
            uint32_t base = r * 33 + q;
            uint32_t h;
            h = tf32_rna(v.x); smu[SM_AH + base + 0] = h;
            smu[SM_AL + base + 0] = tf32_rna(v.x - __uint_as_float(h));
            h = tf32_rna(v.y); smu[SM_AH + base + 1] = h;
            smu[SM_AL + base + 1] = tf32_rna(v.y - __uint_as_float(h));
            h = tf32_rna(v.z); smu[SM_AH + base + 2] = h;
            smu[SM_AL + base + 2] = tf32_rna(v.z - __uint_as_float(h));
            h = tf32_rna(v.w); smu[SM_AH + base + 3] = h;
            smu[SM_AL + base + 3] = tf32_rna(v.w - __uint_as_float(h));
        }

#pragma unroll
        for (int it = 0; it < 4; it++) {
            int idx = tid + it * 256;
            int kk = idx >> 5;
            int n4 = (idx & 31) * 4;
            float4 v = *(const float4*)&Bw[(size_t)(k0 + kk) * G3_ + col0 + n4];
            uint4 hi, lo;
            hi.x = tf32_rna(v.x); lo.x = tf32_rna(v.x - __uint_as_float(hi.x));
            hi.y = tf32_rna(v.y); lo.y = tf32_rna(v.y - __uint_as_float(hi.y));
            hi.z = tf32_rna(v.z); lo.z = tf32_rna(v.z - __uint_as_float(hi.z));
            hi.w = tf32_rna(v.w); lo.w = tf32_rna(v.w - __uint_as_float(hi.w));
            uint32_t base = kk * 132 + n4;
            *(uint4*)&smu[SM_BH + base] = hi;
            *(uint4*)&smu[SM_BL + base] = lo;
        }
        __syncthreads();

#pragma unroll
        for (int ks = 0; ks < 4; ks++) {
            const int kb = ks * 8;
            uint32_t bh[4][2], bl[4][2];
#pragma unroll
            for (int fn = 0; fn < 4; fn++) {
                int n = warp_n * 32 + fn * 8 + tg;
                bh[fn][0] = smu[SM_BH + (kb + tk) * 132 + n];
                bh[fn][1] = smu[SM_BH + (kb + tk + 4) * 132 + n];
                bl[fn][0] = smu[SM_BL + (kb + tk) * 132 + n];
                bl[fn][1] = smu[SM_BL + (kb + tk + 4) * 132 + n];
            }
#pragma unroll
            for (int fm = 0; fm < 4; fm++) {
                int r = warp_m * 64 + fm * 16 + tg;
                uint32_t ah0 = smu[SM_AH + r * 33 + kb + tk];
                uint32_t ah1 = smu[SM_AH + (r + 8) * 33 + kb + tk];
                uint32_t ah2 = smu[SM_AH + r * 33 + kb + tk + 4];
                uint32_t ah3 = smu[SM_AH + (r + 8) * 33 + kb + tk + 4];
                uint32_t al0 = smu[SM_AL + r * 33 + kb + tk];
                uint32_t al1 = smu[SM_AL + (r + 8) * 33 + kb + tk];
                uint32_t al2 = smu[SM_AL + r * 33 + kb + tk + 4];
                uint32_t al3 = smu[SM_AL + (r + 8) * 33 + kb + tk + 4];
#pragma unroll
                for (int fn = 0; fn < 4; fn++) {
                    mma_tf32(acc[fm][fn], ah0, ah1, ah2, ah3,
                             bh[fn][0], bh[fn][1]);
                    mma_tf32(acc[fm][fn], al0, al1, al2, al3,
                             bh[fn][0], bh[fn][1]);
                    mma_tf32(acc[fm][fn], ah0, ah1, ah2, ah3,
                             bl[fn][0], bl[fn][1]);
                }
            }
        }
    }

#pragma unroll
    for (int fm = 0; fm < 4; fm++) {
        int r1 = row0 + warp_m * 64 + fm * 16 + tg;
        int r2 = r1 + 8;
#pragma unroll
        for (int fn = 0; fn < 4; fn++) {
            int col = col0 + warp_n * 32 + fn * 8 + 2 * tk;
            float b0 = bias[col], b1 = bias[col + 1];
            float2 v0 = make_float2(acc[fm][fn][0] + b0, acc[fm][fn][1] + b1);
            float2 v1 = make_float2(acc[fm][fn][2] + b0, acc[fm][fn][3] + b1);
            *(float2*)&C[(size_t)r1 * G3_ + col] = v0;
            *(float2*)&C[(size_t)r2 * G3_ + col] = v1;
        }
    }
}

// ===========================================================================
// Kernel 2: recurrence with st.async h-exchange.
// Per step: wait mbar[p] -> (tid0: re-arm mbar[1-p] expect_tx 2048B) ->
// FMA (12 warps) -> STS red -> syncthreads -> epilogue (64 thr, cc=tid>>1,
// bb=tid&1): reduce + gates + out + shfl-pair -> even-cc: 8x st.async.b64
// (data + complete_tx at each peer's mbar[1-p]).
// ===========================================================================
__global__ void __cluster_dims__(8, 1, 1) __launch_bounds__(384, 1)
gru_recur_kernel(const float* __restrict__ gx,
                 const int* __restrict__ mask,
                 const float* __restrict__ h0,
                 const float* __restrict__ W_hh,
                 const float* __restrict__ b_hh,
                 float* __restrict__ out)
{
    __shared__ __align__(16) float sh_h[2][2][H_];             // [buf][batch][k]
    __shared__ __align__(16) unsigned long long red[2][4][96]; // [batch][s][j]
    __shared__ __align__(8)  unsigned long long mbar[2];
    __shared__ uint32_t mbits[2][64];

    const int tid = threadIdx.x;
    const int j = tid % 96;
    const int s = tid / 96;
    uint32_t rank;
    asm("mov.u32 %0, %%cluster_ctarank;" : "=r"(rank));
    const int cid = blockIdx.x >> 3;
    const int b0  = cid * 2;

    const int piece = j >> 5;
    const int cIn   = j & 31;
    const int gcol  = piece * 256 + (int)rank * 32 + cIn;
    const int k0    = s * 64;

    // ---- W_hh slice: 64 k-values packed as 32 b64 (k, k+1) ----
    unsigned long long wq[32];
#pragma unroll
    for (int i = 0; i < 32; i++) {
        wq[i] = pack2(W_hh[(size_t)(k0 + 2 * i) * G3_ + gcol],
                      W_hh[(size_t)(k0 + 2 * i + 1) * G3_ + gcol]);
    }

    // ---- init h buffer 0, mask bitmasks, mbarriers ----
    for (int i = tid; i < 2 * H_; i += 384) {
        int bbw = i >> 8, k = i & 255;
        sh_h[0][bbw][k] = h0[(size_t)(b0 + bbw) * H_ + k];
    }
    for (int w = tid; w < 128; w += 384) {
        int bbw = w >> 6, word = w & 63;
        const int* mp = mask + (size_t)(b0 + bbw) * T_ + word * 32;
        uint32_t bits = 0;
#pragma unroll
        for (int i = 0; i < 32; i++) bits |= (mp[i] != 0 ? 1u : 0u) << i;
        mbits[bbw][word] = bits;
    }
    const uint32_t sh_base  = smem_u32(&sh_h[0][0][0]);
    const uint32_t mbar_la  = smem_u32(&mbar[0]);
    if (tid == 0) {
        asm volatile("mbarrier.init.shared.b64 [%0], %1;"
                     :: "r"(mbar_la), "r"(1u) : "memory");
        asm volatile("mbarrier.init.shared.b64 [%0], %1;"
                     :: "r"(mbar_la + 8), "r"(1u) : "memory");
    }
    __syncthreads();
    asm volatile("barrier.cluster.arrive.aligned;" ::: "memory");
    asm volatile("barrier.cluster.wait.aligned;" ::: "memory");

    // ---- epilogue-thread constants (threads 0..63: cc = tid>>1, bb = tid&1)
    float bh_r = 0.f, bh_z = 0.f, bh_n = 0.f;
    int cc = 0, bb = 0, hcol = 0;
    const float* gx_b = nullptr;
    float* out_b = nullptr;
    float gr0 = 0.f, gz0 = 0.f, gn0 = 0.f;
    float gr1 = 0.f, gz1 = 0.f, gn1 = 0.f;
    uint32_t peer_sh[8], peer_mb[8];
    if (tid < 64) {
        cc = tid >> 1;
        bb = tid & 1;
        hcol = (int)rank * 32 + cc;
        bh_r = b_hh[hcol];
        bh_z = b_hh[256 + hcol];
        bh_n = b_hh[512 + hcol];
        gx_b  = gx  + (size_t)(b0 + bb) * T_ * G3_;
        out_b = out + (size_t)(b0 + bb) * T_ * H_;
        const float* g0 = gx_b + hcol;
        gr0 = g0[0];   gz0 = g0[256];       gn0 = g0[512];
        gr1 = g0[G3_]; gz1 = g0[G3_ + 256]; gn1 = g0[G3_ + 512];
#pragma unroll
        for (int rr = 0; rr < 8; rr++) {
            asm("mapa.shared::cluster.u32 %0, %1, %2;"
                : "=r"(peer_sh[rr]) : "r"(sh_base), "r"((uint32_t)rr));
            asm("mapa.shared::cluster.u32 %0, %1, %2;"
                : "=r"(peer_mb[rr]) : "r"(mbar_la), "r"((uint32_t)rr));
        }
    }

    uint32_t ph0 = 0, ph1 = 0;

    for (int t = 0; t < T_; t++) {
        const int p = t & 1;

        // ---- wait for h_t ----
        if (t) {
            if (p == 0) { mbar_wait(mbar_la, ph0);     ph0 ^= 1; }
            else        { mbar_wait(mbar_la + 8, ph1); ph1 ^= 1; }
        }

        // ---- re-arm next-phase barrier: 1 arrival + 2048 tx bytes ----
        if (tid == 0) {
            asm volatile("mbarrier.arrive.expect_tx.shared.b64 _, [%0], %1;"
                         :: "r"(mbar_la + (uint32_t)((1 - p) * 8)), "r"(2048u)
                         : "memory");
        }

        // ---- gx shift-register prefetch (depth 2) ----
        float gxr = 0.f, gxz = 0.f, gxn = 0.f;
        int m = 1;
        if (tid < 64) {
            gxr = gr0; gxz = gz0; gxn = gn0;
            gr0 = gr1; gz0 = gz1; gn0 = gn1;
            m = (int)((mbits[bb][t >> 5] >> (t & 31)) & 1u);
            if (t + 2 < T_) {
                const float* g2 = gx_b + (size_t)(t + 2) * G3_ + hcol;
                gr1 = g2[0]; gz1 = g2[256]; gn1 = g2[512];
            }
        }

        // ---- FMA: 2 batches x 32 fma2, W regs shared across batches ----
        unsigned long long a0 = 0ull, a1 = 0ull;
        const ulonglong2* hp0 = (const ulonglong2*)&sh_h[p][0][k0];
        const ulonglong2* hp1 = (const ulonglong2*)&sh_h[p][1][k0];
#pragma unroll
        for (int kk = 0; kk < 16; kk++) {
            ulonglong2 hv = hp0[kk];
            a0 = fma2(wq[2 * kk],     hv.x, a0);
            a0 = fma2(wq[2 * kk + 1], hv.y, a0);
        }
#pragma unroll
        for (int kk = 0; kk < 16; kk++) {
            ulonglong2 hv = hp1[kk];
            a1 = fma2(wq[2 * kk],     hv.x, a1);
            a1 = fma2(wq[2 * kk + 1], hv.y, a1);
        }
        red[0][s][j] = a0;
        red[1][s][j] = a1;
        __syncthreads();

        // ---- epilogue + direct st.async push ----
        if (tid < 64) {
            unsigned long long rr_ = add2(add2(red[bb][0][cc], red[bb][1][cc]),
                                          add2(red[bb][2][cc], red[bb][3][cc]));
            unsigned long long zz_ = add2(add2(red[bb][0][32 + cc], red[bb][1][32 + cc]),
                                          add2(red[bb][2][32 + cc], red[bb][3][32 + cc]));
            unsigned long long nn_ = add2(add2(red[bb][0][64 + cc], red[bb][1][64 + cc]),
                                          add2(red[bb][2][64 + cc], red[bb][3][64 + cc]));
            float2 vr = unpack2(rr_), vz = unpack2(zz_), vn = unpack2(nn_);
            float ghr = vr.x + vr.y;
            float ghz = vz.x + vz.y;
            float ghn = vn.x + vn.y;
            float hold = sh_h[p][bb][hcol];

            float r  = sigmoid_fast(gxr + ghr + bh_r);
            float z  = sigmoid_fast(gxz + ghz + bh_z);
            float n  = tanh_fast(gxn + r * (ghn + bh_n));
            float hnew = (1.0f - z) * n + z * hold;
            if (!m) hnew = hold;

            out_b[(size_t)t * H_ + hcol] = hnew;

            // pair columns (cc, cc^1) within warp: partner tid = tid ^ 2
            float other = __shfl_xor_sync(0xFFFFFFFFu, hnew, 2);
            if ((cc & 1) == 0) {
                unsigned long long val = pack2(hnew, other);  // {h[cc], h[cc+1]}
                uint32_t off = (uint32_t)((((1 - p) * 2 + bb) * H_ + hcol) * 4);
                uint32_t bof = (uint32_t)((1 - p) * 8);
#pragma unroll
                for (int rr = 0; rr < 8; rr++) {
                    asm volatile(
                        "st.async.shared::cluster.mbarrier::complete_tx::bytes.b64 "
                        "[%0], %1, [%2];"
                        :: "r"(peer_sh[rr] + off), "l"(val),
                           "r"(peer_mb[rr] + bof)
                        : "memory");
                }
            }
        }
    }

    asm volatile("barrier.cluster.arrive.aligned;" ::: "memory");
    asm volatile("barrier.cluster.wait.aligned;" ::: "memory");
}

// ===========================================================================
// Launch
// ===========================================================================
extern "C" void kernel_launch(void* const* d_in, const int* in_sizes, int n_in,
                              void* d_out, int out_size)
{
    const float* x    = (const float*)d_in[0];
    const int*   mask = (const int*)d_in[1];
    const float* h0   = (const float*)d_in[2];
    const float* W_ih = (const float*)d_in[3];
    const float* W_hh = (const float*)d_in[4];
    const float* b_ih = (const float*)d_in[5];
    const float* b_hh = (const float*)d_in[6];
    float* out = (float*)d_out;

    float* gx;
    cudaGetSymbolAddress((void**)&gx, g_gx);

    cudaFuncSetAttribute(gemm_gx_mma,
                         cudaFuncAttributeMaxDynamicSharedMemorySize,
                         SM_WORDS * 4);

    dim3 g1(G3_ / 128, (B_ * T_) / 128);   // (6, 512)
    gemm_gx_mma<<<g1, 256, SM_WORDS * 4>>>(x, W_ih, b_ih, gx);

    gru_recur_kernel<<<128, 384>>>(gx, mask, h0, W_hh, b_hh, out);
}